// round 3
// baseline (speedup 1.0000x reference)
#include <cuda_runtime.h>
#include <math.h>

#define N_NODES 20000
#define N_EDGES 400000
#define DNODE 16
#define HID 128
#define WCOLS 512            // 2*D*D

// ---------------- scratch (device globals: no runtime allocation) ----------
__device__ float g_w[(size_t)N_EDGES * WCOLS];   // per-edge [32,16] weight, flat
__device__ float g_h0[N_NODES * DNODE];
__device__ float g_h1[N_NODES * DNODE];
__device__ int   g_ei_mode;                      // 0 = int32 indices, 1 = int64

// selector: 0 -> g_h0, 1 -> g_h1, 2 -> external (d_out region)
__device__ __forceinline__ float* pick_buf(int s, float* ext) {
    if (s == 0) return g_h0;
    if (s == 1) return g_h1;
    return ext;
}
__device__ __forceinline__ const float* pick_cbuf(int s, const float* ext) {
    if (s == 0) return g_h0;
    if (s == 1) return g_h1;
    return ext;
}

// adaptive index load
__device__ __forceinline__ int load_idx(const void* ei, int mode, int i) {
    if (mode) return (int)((const long long*)ei)[i];
    return ((const int*)ei)[i];
}

// ---------------- index dtype detection ------------------------------------
// If edge_index is int64 with values in [0, 20000), every odd 32-bit word is 0.
// For int32 random indices that is (1/20000)^64 ~ impossible.
__global__ void k_detect_ei(const unsigned int* __restrict__ ei_words) {
    if (threadIdx.x == 0 && blockIdx.x == 0) {
        int all_zero = 1;
        for (int i = 0; i < 64; i++)
            if (ei_words[2*i + 1] != 0u) { all_zero = 0; break; }
        g_ei_mode = all_zero;  // 1 -> int64, 0 -> int32
    }
}

// ---------------- f32x2 packed-FMA helpers ---------------------------------
__device__ __forceinline__ unsigned long long pack2(float a, float b) {
    unsigned long long r;
    asm("mov.b64 %0, {%1, %2};" : "=l"(r) : "f"(a), "f"(b));
    return r;
}
__device__ __forceinline__ void unpack2(unsigned long long v, float& a, float& b) {
    asm("mov.b64 {%0, %1}, %2;" : "=f"(a), "=f"(b) : "l"(v));
}
__device__ __forceinline__ unsigned long long fma2(unsigned long long a,
                                                   unsigned long long b,
                                                   unsigned long long c) {
    unsigned long long d;
    asm("fma.rn.f32x2 %0, %1, %2, %3;" : "=l"(d) : "l"(a), "l"(b), "l"(c));
    return d;
}

// ---------------- node embedding: g_h0 = relu(x @ Wn + bn) -----------------
__global__ void k_node_embed(const float* __restrict__ x,
                             const float* __restrict__ Wn,
                             const float* __restrict__ bn) {
    __shared__ float sW[256];
    __shared__ float sb[16];
    int tid = threadIdx.x;
    if (tid < 256) sW[tid] = Wn[tid];
    if (tid < 16) sb[tid] = bn[tid];
    __syncthreads();
    int n = blockIdx.x * blockDim.x + tid;
    if (n >= N_NODES) return;
    float xi[16];
    const float4* xp = (const float4*)(x + (size_t)n * 16);
#pragma unroll
    for (int q = 0; q < 4; q++) {
        float4 v = xp[q];
        xi[4*q] = v.x; xi[4*q+1] = v.y; xi[4*q+2] = v.z; xi[4*q+3] = v.w;
    }
    float o[16];
#pragma unroll
    for (int d = 0; d < 16; d++) {
        float acc = sb[d];
#pragma unroll
        for (int k = 0; k < 16; k++) acc = fmaf(xi[k], sW[k*16+d], acc);
        o[d] = fmaxf(acc, 0.f);
    }
    float4* op = (float4*)(g_h0 + (size_t)n * 16);
#pragma unroll
    for (int q = 0; q < 4; q++) op[q] = make_float4(o[4*q], o[4*q+1], o[4*q+2], o[4*q+3]);
}

// ---------------- root transform: hout = hin @ root + bias (no relu) -------
__global__ void k_root(int sin, int sout, float* ext,
                       const float* __restrict__ root,
                       const float* __restrict__ bias) {
    __shared__ float sW[256];
    __shared__ float sb[16];
    int tid = threadIdx.x;
    if (tid < 256) sW[tid] = root[tid];
    if (tid < 16) sb[tid] = bias[tid];
    __syncthreads();
    const float* hin = pick_cbuf(sin, ext);
    float* hout = pick_buf(sout, ext);
    int n = blockIdx.x * blockDim.x + tid;
    if (n >= N_NODES) return;
    float xi[16];
    const float4* xp = (const float4*)(hin + (size_t)n * 16);
#pragma unroll
    for (int q = 0; q < 4; q++) {
        float4 v = xp[q];
        xi[4*q] = v.x; xi[4*q+1] = v.y; xi[4*q+2] = v.z; xi[4*q+3] = v.w;
    }
    float o[16];
#pragma unroll
    for (int d = 0; d < 16; d++) {
        float acc = sb[d];
#pragma unroll
        for (int k = 0; k < 16; k++) acc = fmaf(xi[k], sW[k*16+d], acc);
        o[d] = acc;
    }
    float4* op = (float4*)(hout + (size_t)n * 16);
#pragma unroll
    for (int q = 0; q < 4; q++) op[q] = make_float4(o[4*q], o[4*q+1], o[4*q+2], o[4*q+3]);
}

// ---------------- edge MLP: g_w = relu(ea@W1+b1)@W2 + b2 -------------------
#define TILE_E 128
#define EMLP_THREADS 256
#define SM_EA 0
#define SM_W1 (128*17)
#define SM_B1 (SM_W1 + 2048)
#define SM_HIDT (SM_B1 + 128)
#define SM_W2 (SM_HIDT + 128*132)
#define SM_TOTAL (SM_W2 + 128*68)          // 29952 floats = 119808 B

__global__ void __launch_bounds__(EMLP_THREADS, 1)
k_edge_mlp(const float* __restrict__ ea,
           const float* __restrict__ W1, const float* __restrict__ b1,
           const float* __restrict__ W2, const float* __restrict__ b2) {
    extern __shared__ float sm[];
    int tid = threadIdx.x;
    int e0 = blockIdx.x * TILE_E;

    for (int idx = tid; idx < TILE_E * 16; idx += EMLP_THREADS) {
        int e = idx >> 4, k = idx & 15;
        sm[SM_EA + e*17 + k] = ea[(size_t)(e0 + e)*16 + k];
    }
    for (int idx = tid; idx < 2048; idx += EMLP_THREADS) sm[SM_W1 + idx] = W1[idx];
    if (tid < 128) sm[SM_B1 + tid] = b1[tid];
    __syncthreads();

    // phase 1: hidden[k][e] = relu(ea[e]·W1[:,k] + b1[k]), stored k-major
    for (int idx = tid; idx < TILE_E * HID; idx += EMLP_THREADS) {
        int e = idx & 127, hc = idx >> 7;
        float acc = sm[SM_B1 + hc];
#pragma unroll
        for (int k = 0; k < 16; k++)
            acc = fmaf(sm[SM_EA + e*17 + k], sm[SM_W1 + k*128 + hc], acc);
        sm[SM_HIDT + hc*132 + e] = fmaxf(acc, 0.f);
    }
    __syncthreads();

    // phase 2: out[e][j] = b2[j] + sum_k hid[e][k] * W2[k][j]
    int te = tid >> 4;           // 0..15 -> 8 edges each (4 f32x2 pairs)
    int tj = tid & 15;           // 0..15 -> 4 cols each
    int ebase = te * 8;
    int jb = tj * 4;

    for (int jt = 0; jt < 8; jt++) {
        for (int idx = tid; idx < 128 * 64; idx += EMLP_THREADS) {
            int k = idx >> 6, j = idx & 63;
            sm[SM_W2 + k*68 + j] = W2[(size_t)k*512 + jt*64 + j];
        }
        __syncthreads();

        unsigned long long acc[4][4];
#pragma unroll
        for (int jj = 0; jj < 4; jj++) {
            float bv = b2[jt*64 + jb + jj];
            unsigned long long bp = pack2(bv, bv);
#pragma unroll
            for (int ep = 0; ep < 4; ep++) acc[ep][jj] = bp;
        }

#pragma unroll 4
        for (int k = 0; k < 128; k++) {
            float4 w4 = *(const float4*)&sm[SM_W2 + k*68 + jb];
            unsigned long long wp0 = pack2(w4.x, w4.x);
            unsigned long long wp1 = pack2(w4.y, w4.y);
            unsigned long long wp2 = pack2(w4.z, w4.z);
            unsigned long long wp3 = pack2(w4.w, w4.w);
            const float* hrow = &sm[SM_HIDT + k*132 + ebase];
            unsigned long long hp[4];
#pragma unroll
            for (int ep = 0; ep < 4; ep++)
                hp[ep] = *(const unsigned long long*)&hrow[2*ep];
#pragma unroll
            for (int ep = 0; ep < 4; ep++) {
                acc[ep][0] = fma2(hp[ep], wp0, acc[ep][0]);
                acc[ep][1] = fma2(hp[ep], wp1, acc[ep][1]);
                acc[ep][2] = fma2(hp[ep], wp2, acc[ep][2]);
                acc[ep][3] = fma2(hp[ep], wp3, acc[ep][3]);
            }
        }

#pragma unroll
        for (int ep = 0; ep < 4; ep++) {
            float lo[4], hi[4];
#pragma unroll
            for (int jj = 0; jj < 4; jj++) unpack2(acc[ep][jj], lo[jj], hi[jj]);
            size_t eL = (size_t)(e0 + ebase + 2*ep);
            *(float4*)&g_w[eL*512 + jt*64 + jb]       = make_float4(lo[0], lo[1], lo[2], lo[3]);
            *(float4*)&g_w[(eL+1)*512 + jt*64 + jb]   = make_float4(hi[0], hi[1], hi[2], hi[3]);
        }
        __syncthreads();
    }
}

// ---------------- message + scatter: hout[dst] += nf · w[e] ----------------
__global__ void k_msg(const void* __restrict__ ei,
                      int sin, int sout, float* ext) {
    const float* h = pick_cbuf(sin, ext);
    float* hout = pick_buf(sout, ext);
    int mode = g_ei_mode;
    int warp = (blockIdx.x * blockDim.x + threadIdx.x) >> 5;
    int lane = threadIdx.x & 31;
    if (warp >= N_EDGES) return;
    int srcn = load_idx(ei, mode, warp);
    int dstn = load_idx(ei, mode, N_EDGES + warp);
    float myf = (lane < 16) ? h[(size_t)dstn*16 + lane] : h[(size_t)srcn*16 + (lane - 16)];
    float4 acc = make_float4(0.f, 0.f, 0.f, 0.f);
    const float4* wrow = (const float4*)&g_w[(size_t)warp * WCOLS];
#pragma unroll
    for (int it = 0; it < 4; it++) {
        int idx = it*32 + lane;
        int row = idx >> 2;
        float4 wv = wrow[idx];
        float nfr = __shfl_sync(0xffffffffu, myf, row);
        acc.x = fmaf(nfr, wv.x, acc.x);
        acc.y = fmaf(nfr, wv.y, acc.y);
        acc.z = fmaf(nfr, wv.z, acc.z);
        acc.w = fmaf(nfr, wv.w, acc.w);
    }
#pragma unroll
    for (int off = 4; off < 32; off <<= 1) {
        acc.x += __shfl_xor_sync(0xffffffffu, acc.x, off);
        acc.y += __shfl_xor_sync(0xffffffffu, acc.y, off);
        acc.z += __shfl_xor_sync(0xffffffffu, acc.z, off);
        acc.w += __shfl_xor_sync(0xffffffffu, acc.w, off);
    }
    if (lane < 4) {
        float* o = hout + (size_t)dstn*16 + lane*4;
        atomicAdd(o + 0, acc.x);
        atomicAdd(o + 1, acc.y);
        atomicAdd(o + 2, acc.z);
        atomicAdd(o + 3, acc.w);
    }
}

// ---------------- edge embedding + log_softmax -----------------------------
__global__ void k_edge_embed(const float* __restrict__ ea,
                             const float* __restrict__ We,
                             const float* __restrict__ be,
                             float* __restrict__ ee_out,
                             float* __restrict__ lsm_out,
                             int n_ee, int n_lsm) {
    __shared__ float sW[256];
    __shared__ float sb[16];
    int tid = threadIdx.x;
    if (tid < 256) sW[tid] = We[tid];
    if (tid < 16) sb[tid] = be[tid];
    __syncthreads();
    int e = blockIdx.x * blockDim.x + tid;
    if (e >= N_EDGES) return;
    float xi[16];
    const float4* xp = (const float4*)(ea + (size_t)e * 16);
#pragma unroll
    for (int q = 0; q < 4; q++) {
        float4 v = xp[q];
        xi[4*q] = v.x; xi[4*q+1] = v.y; xi[4*q+2] = v.z; xi[4*q+3] = v.w;
    }
    float v[16];
    float m = -1e30f;
#pragma unroll
    for (int d = 0; d < 16; d++) {
        float acc = sb[d];
#pragma unroll
        for (int k = 0; k < 16; k++) acc = fmaf(xi[k], sW[k*16+d], acc);
        v[d] = fmaxf(acc, 0.f);
        m = fmaxf(m, v[d]);
    }
    float s = 0.f;
#pragma unroll
    for (int d = 0; d < 16; d++) s += expf(v[d] - m);
    float ls = m + logf(s);
    if (e < n_ee) {
        float4* eo = (float4*)(ee_out + (size_t)e * 16);
#pragma unroll
        for (int q = 0; q < 4; q++)
            eo[q] = make_float4(v[4*q], v[4*q+1], v[4*q+2], v[4*q+3]);
    }
    if (e < n_lsm) {
        float4* lo = (float4*)(lsm_out + (size_t)e * 16);
#pragma unroll
        for (int q = 0; q < 4; q++)
            lo[q] = make_float4(v[4*q] - ls, v[4*q+1] - ls, v[4*q+2] - ls, v[4*q+3] - ls);
    }
}

// ---------------- edge_index passthrough (cast to f32) ----------------------
__global__ void k_ei_copy(const void* __restrict__ ei, float* __restrict__ out,
                          int n_vals) {
    int mode = g_ei_mode;
    int i = blockIdx.x * blockDim.x + threadIdx.x;
    if (i >= n_vals) return;
    out[i] = (float)load_idx(ei, mode, i);
}

// ---------------- launch ----------------------------------------------------
extern "C" void kernel_launch(void* const* d_in, const int* in_sizes, int n_in,
                              void* d_out, int out_size) {
    const float* x     = (const float*)d_in[0];
    const void*  ei    = d_in[1];
    const float* ea    = (const float*)d_in[2];
    const float* Wn    = (const float*)d_in[3];
    const float* bn    = (const float*)d_in[4];
    const float* We    = (const float*)d_in[5];
    const float* be    = (const float*)d_in[6];
    const float* W1    = (const float*)d_in[7];
    const float* b1    = (const float*)d_in[8];
    const float* W2    = (const float*)d_in[9];
    const float* b2    = (const float*)d_in[10];
    const float* root1 = (const float*)d_in[11];
    const float* bias1 = (const float*)d_in[12];
    const float* root2 = (const float*)d_in[13];
    const float* bias2 = (const float*)d_in[14];

    float* out = (float*)d_out;
    size_t cap = (size_t)out_size;

    // ---- derive output layout from out_size ----
    // A: [h(320000) | ei as f32 (800000) | ee(6400000) | lsm(6400000)] = 13,920,000
    // C: [h | ee | lsm] (edge_index omitted)                           = 13,120,000
    size_t ei_slots = (cap == 13120000) ? 0 : 2ull * N_EDGES;

    size_t off_h   = 0;
    size_t off_ei  = off_h + (size_t)N_NODES * 16;
    size_t off_ee  = off_ei + ei_slots;
    size_t off_lsm = off_ee + (size_t)N_EDGES * 16;

    auto avail = [&](size_t off) -> size_t { return off < cap ? cap - off : 0; };

    float* out_h   = out + off_h;
    float* out_ei  = out + off_ei;
    float* out_ee  = out + off_ee;
    float* out_lsm = out + off_lsm;

    bool h_fits = avail(off_h) >= (size_t)N_NODES * 16;
    int  n_ei   = ei_slots ? (int)min((size_t)(2 * N_EDGES), avail(off_ei)) : 0;
    int  n_ee   = (int)min((size_t)N_EDGES, avail(off_ee) / 16);
    int  n_lsm  = (int)min((size_t)N_EDGES, avail(off_lsm) / 16);

    cudaFuncSetAttribute(k_edge_mlp, cudaFuncAttributeMaxDynamicSharedMemorySize,
                         SM_TOTAL * (int)sizeof(float));

    // detect edge_index dtype (int32 vs int64) -> g_ei_mode
    k_detect_ei<<<1, 32>>>((const unsigned int*)ei);

    // node embedding -> g_h0
    k_node_embed<<<(N_NODES + 255) / 256, 256>>>(x, Wn, bn);
    // shared per-edge weights (used by both conv layers) -> g_w
    k_edge_mlp<<<N_EDGES / TILE_E, EMLP_THREADS, SM_TOTAL * sizeof(float)>>>(ea, W1, b1, W2, b2);

    // conv layer 1: g_h1 = root(g_h0) + scatter(msg(g_h0))
    k_root<<<(N_NODES + 255) / 256, 256>>>(0, 1, out_h, root1, bias1);
    k_msg<<<(N_EDGES * 32 + 255) / 256, 256>>>(ei, 0, 1, out_h);

    // conv layer 2: out_h = root(g_h1) + scatter(msg(g_h1))
    int sout2 = h_fits ? 2 : 0;
    k_root<<<(N_NODES + 255) / 256, 256>>>(1, sout2, out_h, root2, bias2);
    k_msg<<<(N_EDGES * 32 + 255) / 256, 256>>>(ei, 1, sout2, out_h);

    // edge embedding + log_softmax
    if (n_ee > 0 || n_lsm > 0)
        k_edge_embed<<<(N_EDGES + 255) / 256, 256>>>(ea, We, be, out_ee, out_lsm,
                                                     n_ee, n_lsm);
    // edge_index passthrough
    if (n_ei > 0)
        k_ei_copy<<<(n_ei + 255) / 256, 256>>>(ei, out_ei, n_ei);
}

// round 4
// speedup vs baseline: 1.3082x; 1.3082x over previous
#include <cuda_runtime.h>
#include <math.h>

#define N_NODES 20000
#define N_EDGES 400000
#define HID 128

// ---------------- scratch (device globals) ----------------------------------
__device__ float g_hid[(size_t)N_EDGES * HID];   // relu(ea@W1+b1), layer-shared
__device__ float g_h0[N_NODES * 16];
__device__ float g_h1[N_NODES * 16];
__device__ int   g_deg[N_NODES];
__device__ int   g_off[N_NODES + 1];
__device__ int   g_cursor[N_NODES];
__device__ int   g_csr[N_EDGES];
__device__ int   g_ei_mode;                      // 0 = int32 indices, 1 = int64

__device__ __forceinline__ float* pick_buf(int s, float* ext) {
    if (s == 0) return g_h0;
    if (s == 1) return g_h1;
    return ext;
}
__device__ __forceinline__ const float* pick_cbuf(int s, const float* ext) {
    if (s == 0) return g_h0;
    if (s == 1) return g_h1;
    return ext;
}
__device__ __forceinline__ int load_idx(const void* ei, int mode, int i) {
    if (mode) return (int)((const long long*)ei)[i];
    return ((const int*)ei)[i];
}

// ---------------- index dtype detection ------------------------------------
__global__ void k_detect_ei(const unsigned int* __restrict__ ei_words) {
    if (threadIdx.x == 0 && blockIdx.x == 0) {
        int all_zero = 1;
        for (int i = 0; i < 64; i++)
            if (ei_words[2*i + 1] != 0u) { all_zero = 0; break; }
        g_ei_mode = all_zero;  // 1 -> int64, 0 -> int32
    }
}

// ---------------- CSR build (group edges by dst) ----------------------------
__global__ void k_zero_deg() {
    int i = blockIdx.x * blockDim.x + threadIdx.x;
    if (i < N_NODES) { g_deg[i] = 0; g_cursor[i] = 0; }
}
__global__ void k_count(const void* __restrict__ ei) {
    int mode = g_ei_mode;
    int e = blockIdx.x * blockDim.x + threadIdx.x;
    if (e < N_EDGES) {
        int d = load_idx(ei, mode, N_EDGES + e);
        atomicAdd(&g_deg[d], 1);
    }
}
__global__ void __launch_bounds__(1024) k_scan() {
    __shared__ int sm[1024];
    int t = threadIdx.x;
    int base = t * 20;
    int vals[20];
    int local = 0;
#pragma unroll
    for (int i = 0; i < 20; i++) {
        int idx = base + i;
        vals[i] = (idx < N_NODES) ? g_deg[idx] : 0;
        local += vals[i];
    }
    sm[t] = local;
    __syncthreads();
    for (int off = 1; off < 1024; off <<= 1) {
        int v = (t >= off) ? sm[t - off] : 0;
        __syncthreads();
        sm[t] += v;
        __syncthreads();
    }
    int run = sm[t] - local;   // exclusive prefix for this thread's range
#pragma unroll
    for (int i = 0; i < 20; i++) {
        int idx = base + i;
        if (idx < N_NODES) { g_off[idx] = run; run += vals[i]; }
    }
    if (t == 0) g_off[N_NODES] = N_EDGES;
}
__global__ void k_fill(const void* __restrict__ ei) {
    int mode = g_ei_mode;
    int e = blockIdx.x * blockDim.x + threadIdx.x;
    if (e < N_EDGES) {
        int d = load_idx(ei, mode, N_EDGES + e);
        int pos = g_off[d] + atomicAdd(&g_cursor[d], 1);
        g_csr[pos] = e;
    }
}

// ---------------- node embedding: g_h0 = relu(x @ Wn + bn) -----------------
__global__ void k_node_embed(const float* __restrict__ x,
                             const float* __restrict__ Wn,
                             const float* __restrict__ bn) {
    __shared__ float sW[256];
    __shared__ float sb[16];
    int tid = threadIdx.x;
    if (tid < 256) sW[tid] = Wn[tid];
    if (tid < 16) sb[tid] = bn[tid];
    __syncthreads();
    int n = blockIdx.x * blockDim.x + tid;
    if (n >= N_NODES) return;
    float xi[16];
    const float4* xp = (const float4*)(x + (size_t)n * 16);
#pragma unroll
    for (int q = 0; q < 4; q++) {
        float4 v = xp[q];
        xi[4*q] = v.x; xi[4*q+1] = v.y; xi[4*q+2] = v.z; xi[4*q+3] = v.w;
    }
    float o[16];
#pragma unroll
    for (int d = 0; d < 16; d++) {
        float acc = sb[d];
#pragma unroll
        for (int k = 0; k < 16; k++) acc = fmaf(xi[k], sW[k*16+d], acc);
        o[d] = fmaxf(acc, 0.f);
    }
    float4* op = (float4*)(g_h0 + (size_t)n * 16);
#pragma unroll
    for (int q = 0; q < 4; q++) op[q] = make_float4(o[4*q], o[4*q+1], o[4*q+2], o[4*q+3]);
}

// ---------------- hidden: g_hid = relu(ea @ W1 + b1) ------------------------
#define HID_EPB 64
__global__ void __launch_bounds__(256) k_hid(const float* __restrict__ ea,
                                             const float* __restrict__ W1,
                                             const float* __restrict__ b1) {
    __shared__ float sEA[HID_EPB * 17];
    __shared__ float sW1[16 * 128];
    __shared__ float sB1[128];
    int tid = threadIdx.x;
    int e0 = blockIdx.x * HID_EPB;
    for (int idx = tid; idx < HID_EPB * 16; idx += 256) {
        int e = idx >> 4, k = idx & 15;
        sEA[e*17 + k] = ea[(size_t)(e0 + e)*16 + k];
    }
    for (int idx = tid; idx < 2048; idx += 256) sW1[idx] = W1[idx];
    if (tid < 128) sB1[tid] = b1[tid];
    __syncthreads();

    int el = tid >> 2;      // edge within block (0..63)
    int p  = tid & 3;       // unit quarter: [p*32, p*32+32)
    float a[16];
#pragma unroll
    for (int k = 0; k < 16; k++) a[k] = sEA[el*17 + k];
    float* outp = g_hid + (size_t)(e0 + el) * 128 + p * 32;
#pragma unroll
    for (int uu = 0; uu < 32; uu += 4) {
        int ub = p*32 + uu;
        float acc0 = sB1[ub+0], acc1 = sB1[ub+1], acc2 = sB1[ub+2], acc3 = sB1[ub+3];
#pragma unroll
        for (int k = 0; k < 16; k++) {
            float av = a[k];
            const float* wr = &sW1[k*128 + ub];
            acc0 = fmaf(av, wr[0], acc0);
            acc1 = fmaf(av, wr[1], acc1);
            acc2 = fmaf(av, wr[2], acc2);
            acc3 = fmaf(av, wr[3], acc3);
        }
        *(float4*)(outp + uu) = make_float4(fmaxf(acc0, 0.f), fmaxf(acc1, 0.f),
                                            fmaxf(acc2, 0.f), fmaxf(acc3, 0.f));
    }
}

// ---------------- fused graph conv (per-node contraction) -------------------
// out[n][d] = bias[d] + h[n]@root
//           + deg(n)*sum_{r<16} b2[r,d] h[n][r] + sum_j b2[16+j,d] Hs[n][j]
//           + sum_k Hsum[n][k] sum_{r<16} W2[k][r,d] h[n][r]
//           + sum_{k,j} W2[k][16+j,d] T[n][k][j]
// where Hsum = segsum(hid), Hs = segsum(h[src]), T = segsum(hid ⊗ h[src]).
#define CONV_THREADS 512
#define NODES_PB 16
#define KC 32
#define NCHUNK 4
#define SW2_PITCH 33
#define CONV_SMEM (512 * SW2_PITCH * 4)   // 67584 bytes

__global__ void __launch_bounds__(CONV_THREADS) k_conv(
    int sin, int sout, float* ext,
    const void* __restrict__ ei,
    const float* __restrict__ W2, const float* __restrict__ b2,
    const float* __restrict__ root, const float* __restrict__ bias) {
    extern __shared__ float sW2T[];   // [rd 0..511][k 0..31], pitch 33
    const float* hin = pick_cbuf(sin, ext);
    float* hout = pick_buf(sout, ext);
    int mode = g_ei_mode;
    int tid = threadIdx.x;
    int wid = tid >> 5, l = tid & 31;
    int n = blockIdx.x * NODES_PB + wid;      // grid is exact: 1250*16 = 20000

    int start = g_off[n], end = g_off[n + 1];
    float h_n = (l < 16) ? hin[(size_t)n * 16 + l] : 0.f;

    float partial[16];
#pragma unroll
    for (int d = 0; d < 16; d++) partial[d] = 0.f;
    float Hs = 0.f;

    for (int c = 0; c < NCHUNK; c++) {
        __syncthreads();
        // stage W2 chunk c transposed: sW2T[rd*33 + k_local] = W2[(c*32+k)*512 + rd]
        for (int idx = tid; idx < KC * 512; idx += CONV_THREADS) {
            int kl = idx >> 9, rd = idx & 511;
            sW2T[rd * SW2_PITCH + kl] = W2[(size_t)c * (KC * 512) + idx];
        }
        __syncthreads();

        float T[16];
#pragma unroll
        for (int j = 0; j < 16; j++) T[j] = 0.f;
        float Hsum = 0.f;

        for (int pos = start; pos < end; pos++) {
            int e = g_csr[pos];
            int srcn = load_idx(ei, mode, e);
            float hv = (l < 16) ? hin[(size_t)srcn * 16 + l] : 0.f;
            float hd = g_hid[(size_t)e * 128 + c * KC + l];
            Hsum += hd;
            if (c == 0) Hs += hv;
#pragma unroll
            for (int j = 0; j < 16; j++) {
                float hj = __shfl_sync(0xffffffffu, hv, j);
                T[j] = fmaf(hd, hj, T[j]);
            }
        }

        // contraction: dst half (r<16) uses Hsum * h[n][r]
#pragma unroll
        for (int r = 0; r < 16; r++) {
            float hr = __shfl_sync(0xffffffffu, h_n, r);
            float ar = Hsum * hr;
#pragma unroll
            for (int d = 0; d < 16; d++)
                partial[d] = fmaf(ar, sW2T[(r * 16 + d) * SW2_PITCH + l], partial[d]);
        }
        // src half (r = 16+j) uses T[j]
#pragma unroll
        for (int j = 0; j < 16; j++) {
            float tj = T[j];
#pragma unroll
            for (int d = 0; d < 16; d++)
                partial[d] = fmaf(tj, sW2T[((16 + j) * 16 + d) * SW2_PITCH + l], partial[d]);
        }
    }

    // epilogue terms on lanes < 16 (lane = r / j index)
    if (l < 16) {
        float dg = (float)(end - start);
        float c0 = dg * h_n;
#pragma unroll
        for (int d = 0; d < 16; d++) {
            partial[d] = fmaf(c0, b2[l * 16 + d], partial[d]);
            partial[d] = fmaf(Hs, b2[(16 + l) * 16 + d], partial[d]);
            partial[d] = fmaf(h_n, root[l * 16 + d], partial[d]);
        }
    }

    // warp reduce all 16 outputs
#pragma unroll
    for (int off = 16; off >= 1; off >>= 1) {
#pragma unroll
        for (int d = 0; d < 16; d++)
            partial[d] += __shfl_xor_sync(0xffffffffu, partial[d], off);
    }
    if (l < 16) hout[(size_t)n * 16 + l] = partial[l] + bias[l];
}

// ---------------- edge embedding + log_softmax -----------------------------
__global__ void k_edge_embed(const float* __restrict__ ea,
                             const float* __restrict__ We,
                             const float* __restrict__ be,
                             float* __restrict__ ee_out,
                             float* __restrict__ lsm_out,
                             int n_ee, int n_lsm) {
    __shared__ float sW[256];
    __shared__ float sb[16];
    int tid = threadIdx.x;
    if (tid < 256) sW[tid] = We[tid];
    if (tid < 16) sb[tid] = be[tid];
    __syncthreads();
    int e = blockIdx.x * blockDim.x + tid;
    if (e >= N_EDGES) return;
    float xi[16];
    const float4* xp = (const float4*)(ea + (size_t)e * 16);
#pragma unroll
    for (int q = 0; q < 4; q++) {
        float4 v = xp[q];
        xi[4*q] = v.x; xi[4*q+1] = v.y; xi[4*q+2] = v.z; xi[4*q+3] = v.w;
    }
    float v[16];
    float m = -1e30f;
#pragma unroll
    for (int d = 0; d < 16; d++) {
        float acc = sb[d];
#pragma unroll
        for (int k = 0; k < 16; k++) acc = fmaf(xi[k], sW[k*16+d], acc);
        v[d] = fmaxf(acc, 0.f);
        m = fmaxf(m, v[d]);
    }
    float s = 0.f;
#pragma unroll
    for (int d = 0; d < 16; d++) s += expf(v[d] - m);
    float ls = m + logf(s);
    if (e < n_ee) {
        float4* eo = (float4*)(ee_out + (size_t)e * 16);
#pragma unroll
        for (int q = 0; q < 4; q++)
            eo[q] = make_float4(v[4*q], v[4*q+1], v[4*q+2], v[4*q+3]);
    }
    if (e < n_lsm) {
        float4* lo = (float4*)(lsm_out + (size_t)e * 16);
#pragma unroll
        for (int q = 0; q < 4; q++)
            lo[q] = make_float4(v[4*q] - ls, v[4*q+1] - ls, v[4*q+2] - ls, v[4*q+3] - ls);
    }
}

// ---------------- edge_index passthrough (cast to f32) ----------------------
__global__ void k_ei_copy(const void* __restrict__ ei, float* __restrict__ out,
                          int n_vals) {
    int mode = g_ei_mode;
    int i = blockIdx.x * blockDim.x + threadIdx.x;
    if (i >= n_vals) return;
    out[i] = (float)load_idx(ei, mode, i);
}

// ---------------- launch ----------------------------------------------------
extern "C" void kernel_launch(void* const* d_in, const int* in_sizes, int n_in,
                              void* d_out, int out_size) {
    const float* x     = (const float*)d_in[0];
    const void*  ei    = d_in[1];
    const float* ea    = (const float*)d_in[2];
    const float* Wn    = (const float*)d_in[3];
    const float* bn    = (const float*)d_in[4];
    const float* We    = (const float*)d_in[5];
    const float* be    = (const float*)d_in[6];
    const float* W1    = (const float*)d_in[7];
    const float* b1    = (const float*)d_in[8];
    const float* W2    = (const float*)d_in[9];
    const float* b2    = (const float*)d_in[10];
    const float* root1 = (const float*)d_in[11];
    const float* bias1 = (const float*)d_in[12];
    const float* root2 = (const float*)d_in[13];
    const float* bias2 = (const float*)d_in[14];

    float* out = (float*)d_out;
    size_t cap = (size_t)out_size;

    // output layout derived from out_size (same logic that passed R3)
    size_t ei_slots = (cap == 13120000) ? 0 : 2ull * N_EDGES;
    size_t off_h   = 0;
    size_t off_ei  = off_h + (size_t)N_NODES * 16;
    size_t off_ee  = off_ei + ei_slots;
    size_t off_lsm = off_ee + (size_t)N_EDGES * 16;
    auto avail = [&](size_t off) -> size_t { return off < cap ? cap - off : 0; };

    float* out_h   = out + off_h;
    float* out_ei  = out + off_ei;
    float* out_ee  = out + off_ee;
    float* out_lsm = out + off_lsm;

    bool h_fits = avail(off_h) >= (size_t)N_NODES * 16;
    int  n_ei   = ei_slots ? (int)min((size_t)(2 * N_EDGES), avail(off_ei)) : 0;
    int  n_ee   = (int)min((size_t)N_EDGES, avail(off_ee) / 16);
    int  n_lsm  = (int)min((size_t)N_EDGES, avail(off_lsm) / 16);

    cudaFuncSetAttribute(k_conv, cudaFuncAttributeMaxDynamicSharedMemorySize,
                         CONV_SMEM);

    // dtype detection + CSR build
    k_detect_ei<<<1, 32>>>((const unsigned int*)ei);
    k_zero_deg<<<(N_NODES + 255) / 256, 256>>>();
    k_count<<<(N_EDGES + 255) / 256, 256>>>(ei);
    k_scan<<<1, 1024>>>();
    k_fill<<<(N_EDGES + 255) / 256, 256>>>(ei);

    // node embedding + shared hidden activations
    k_node_embed<<<(N_NODES + 255) / 256, 256>>>(x, Wn, bn);
    k_hid<<<N_EDGES / HID_EPB, 256>>>(ea, W1, b1);

    // conv layer 1: g_h0 -> g_h1
    k_conv<<<N_NODES / NODES_PB, CONV_THREADS, CONV_SMEM>>>(
        0, 1, out_h, ei, W2, b2, root1, bias1);
    // conv layer 2: g_h1 -> out_h
    int sout2 = h_fits ? 2 : 0;
    k_conv<<<N_NODES / NODES_PB, CONV_THREADS, CONV_SMEM>>>(
        1, sout2, out_h, ei, W2, b2, root2, bias2);

    // edge embedding + log_softmax
    if (n_ee > 0 || n_lsm > 0)
        k_edge_embed<<<(N_EDGES + 255) / 256, 256>>>(ea, We, be, out_ee, out_lsm,
                                                     n_ee, n_lsm);
    if (n_ei > 0)
        k_ei_copy<<<(n_ei + 255) / 256, 256>>>(ei, out_ei, n_ei);
}

// round 5
// speedup vs baseline: 2.1159x; 1.6175x over previous
#include <cuda_runtime.h>
#include <math.h>

#define N_NODES 20000
#define N_EDGES 400000
typedef unsigned long long ull;

// ---------------- scratch (device globals, zero-initialized) ---------------
__device__ float g_h0[N_NODES * 16];
__device__ float g_h1[N_NODES * 16];
__device__ int   g_deg[N_NODES];       // re-zeroed by k_fill each run
__device__ int   g_cursor[N_NODES];    // re-zeroed by k_scan each run
__device__ int   g_off[N_NODES + 1];
__device__ int2  g_es[N_EDGES];        // (edge id, src node) sorted by dst

__device__ __forceinline__ float* pick_buf(int s, float* ext) {
    if (s == 0) return g_h0;
    if (s == 1) return g_h1;
    return ext;
}
__device__ __forceinline__ const float* pick_cbuf(int s, const float* ext) {
    if (s == 0) return g_h0;
    if (s == 1) return g_h1;
    return ext;
}

// ---------------- f32x2 helpers ---------------------------------------------
__device__ __forceinline__ ull pack2(float a, float b) {
    ull r; asm("mov.b64 %0, {%1, %2};" : "=l"(r) : "f"(a), "f"(b)); return r;
}
__device__ __forceinline__ void unpack2(ull v, float& a, float& b) {
    asm("mov.b64 {%0, %1}, %2;" : "=f"(a), "=f"(b) : "l"(v));
}
__device__ __forceinline__ ull fma2(ull a, ull b, ull c) {
    ull d; asm("fma.rn.f32x2 %0, %1, %2, %3;" : "=l"(d) : "l"(a), "l"(b), "l"(c));
    return d;
}

// ---------------- launch 0: degree count + node embedding ------------------
#define COUNT_BLOCKS 1563           // ceil(400000/256)
#define EMBED_BLOCKS 79             // ceil(20000/256)
__global__ void k_count_embed(const int* __restrict__ ei,
                              const float* __restrict__ x,
                              const float* __restrict__ Wn,
                              const float* __restrict__ bn) {
    int b = blockIdx.x;
    if (b < COUNT_BLOCKS) {
        int e = b * 256 + threadIdx.x;
        if (e < N_EDGES) atomicAdd(&g_deg[ei[N_EDGES + e]], 1);
    } else {
        __shared__ float sW[256];
        __shared__ float sb[16];
        int tid = threadIdx.x;
        sW[tid] = Wn[tid];
        if (tid < 16) sb[tid] = bn[tid];
        __syncthreads();
        int n = (b - COUNT_BLOCKS) * 256 + tid;
        if (n >= N_NODES) return;
        float xi[16];
        const float4* xp = (const float4*)(x + (size_t)n * 16);
#pragma unroll
        for (int q = 0; q < 4; q++) {
            float4 v = xp[q];
            xi[4*q] = v.x; xi[4*q+1] = v.y; xi[4*q+2] = v.z; xi[4*q+3] = v.w;
        }
        float o[16];
#pragma unroll
        for (int d = 0; d < 16; d++) {
            float acc = sb[d];
#pragma unroll
            for (int k = 0; k < 16; k++) acc = fmaf(xi[k], sW[k*16+d], acc);
            o[d] = fmaxf(acc, 0.f);
        }
        float4* op = (float4*)(g_h0 + (size_t)n * 16);
#pragma unroll
        for (int q = 0; q < 4; q++)
            op[q] = make_float4(o[4*q], o[4*q+1], o[4*q+2], o[4*q+3]);
    }
}

// ---------------- launch 1: prefix scan (+ re-zero cursor) ------------------
__global__ void __launch_bounds__(1024) k_scan() {
    __shared__ int sm[1024];
    int t = threadIdx.x;
    int base = t * 20;
    int vals[20];
    int local = 0;
#pragma unroll
    for (int i = 0; i < 20; i++) {
        int idx = base + i;
        vals[i] = (idx < N_NODES) ? g_deg[idx] : 0;
        local += vals[i];
    }
    sm[t] = local;
    __syncthreads();
    for (int off = 1; off < 1024; off <<= 1) {
        int v = (t >= off) ? sm[t - off] : 0;
        __syncthreads();
        sm[t] += v;
        __syncthreads();
    }
    int run = sm[t] - local;
#pragma unroll
    for (int i = 0; i < 20; i++) {
        int idx = base + i;
        if (idx < N_NODES) { g_off[idx] = run; run += vals[i]; g_cursor[idx] = 0; }
    }
    if (t == 0) g_off[N_NODES] = N_EDGES;
}

// ---------------- launch 2: fill sorted edge list (+ re-zero deg) -----------
__global__ void k_fill(const int* __restrict__ ei) {
    int e = blockIdx.x * blockDim.x + threadIdx.x;
    if (e < N_EDGES) {
        int d = ei[N_EDGES + e];
        int pos = g_off[d] + atomicAdd(&g_cursor[d], 1);
        g_es[pos] = make_int2(e, ei[e]);
    }
    if (e < N_NODES) g_deg[e] = 0;
}

// ---------------- launch 3/4: fused graph conv ------------------------------
// out[n][d] = bias[d] + h[n]@root + deg(n)*Σ_r b2[r,d] h[n][r] + Σ_j b2[16+j,d] Hs[n][j]
//           + Σ_k Hsum[n][k] Σ_r W2[k][r,d] h[n][r] + Σ_{k,j} W2[k][16+j,d] T[n][k][j]
// hid recomputed on the fly: hid[e][k] = relu(b1[k] + Σ_q ea[e][q] W1[q][k]).
#define CONV_T 256
#define SW2_PITCH 516
#define CONV_DSMEM (32 * SW2_PITCH * 4)   // 66048 B

__device__ __forceinline__ void edge_accum(
    int pstart, int pend, int c, int l, int kk, float b1k,
    const float* __restrict__ hin, const float* __restrict__ ea,
    const ull* __restrict__ sW1p,
    ull T[8], float& Hsum, float& Hs) {
    for (int pos = pstart; pos < pend; pos++) {
        int2 es = g_es[pos];
        int e = es.x, s = es.y;
        if (c == 0 && l < 16) Hs += hin[(size_t)s * 16 + l];
        // uniform 16B loads of ea row and h[src] row (broadcast across lanes)
        ull ev[8], hv[8];
        const ulonglong2* eap = (const ulonglong2*)(ea + (size_t)e * 16);
        const ulonglong2* hjp = (const ulonglong2*)(hin + (size_t)s * 16);
#pragma unroll
        for (int q4 = 0; q4 < 4; q4++) {
            ulonglong2 t1 = eap[q4]; ev[2*q4] = t1.x; ev[2*q4+1] = t1.y;
            ulonglong2 t2 = hjp[q4]; hv[2*q4] = t2.x; hv[2*q4+1] = t2.y;
        }
        // hid[e][kk] via packed-q FMAs
        ull acc = pack2(b1k, 0.f);
#pragma unroll
        for (int qq = 0; qq < 8; qq++)
            acc = fma2(ev[qq], sW1p[qq * 128 + kk], acc);
        float a0, a1; unpack2(acc, a0, a1);
        float hd = fmaxf(a0 + a1, 0.f);
        Hsum += hd;
        ull hd2 = pack2(hd, hd);
#pragma unroll
        for (int jj = 0; jj < 8; jj++) T[jj] = fma2(hd2, hv[jj], T[jj]);
    }
}

__global__ void __launch_bounds__(CONV_T, 2) k_conv(
    int sin, int sout, float* ext,
    const float* __restrict__ ea,
    const float* __restrict__ W1, const float* __restrict__ b1,
    const float* __restrict__ W2, const float* __restrict__ b2,
    const float* __restrict__ root, const float* __restrict__ bias) {
    extern __shared__ float sW2[];           // [32][516] chunk of W2, k-major rows
    __shared__ ull   sW1p[8 * 128];          // (W1[2q][k], W1[2q+1][k])
    __shared__ float sB1[128];
    const float* hin = pick_cbuf(sin, ext);
    float* hout = pick_buf(sout, ext);
    int tid = threadIdx.x, wid = tid >> 5, l = tid & 31;

    for (int i = tid; i < 1024; i += CONV_T) {
        int qq = i >> 7, k = i & 127;
        sW1p[i] = pack2(W1[(2*qq) * 128 + k], W1[(2*qq+1) * 128 + k]);
    }
    if (tid < 128) sB1[tid] = b1[tid];

    int nA = blockIdx.x * 16 + wid * 2;
    int nB = nA + 1;
    int sA = g_off[nA], eA = g_off[nA + 1];
    int sB = g_off[nB], eB = g_off[nB + 1];
    float hA = (l < 16) ? hin[(size_t)nA * 16 + l] : 0.f;
    float hB = (l < 16) ? hin[(size_t)nB * 16 + l] : 0.f;

    ull pA[8], pB[8];
#pragma unroll
    for (int i = 0; i < 8; i++) { pA[i] = 0ull; pB[i] = 0ull; }
    float HsA = 0.f, HsB = 0.f;

    for (int c = 0; c < 4; c++) {
        __syncthreads();
        for (int i = tid; i < 32 * 128; i += CONV_T) {
            int kl = i >> 7, r4 = i & 127;
            float4 w = ((const float4*)W2)[(size_t)(c * 32 + kl) * 128 + r4];
            *(float4*)&sW2[kl * SW2_PITCH + r4 * 4] = w;
        }
        __syncthreads();

        int kk = c * 32 + l;
        float b1k = sB1[kk];

        ull tA[8], tB[8];
#pragma unroll
        for (int i = 0; i < 8; i++) { tA[i] = 0ull; tB[i] = 0ull; }
        float HsumA = 0.f, HsumB = 0.f;
        edge_accum(sA, eA, c, l, kk, b1k, hin, ea, sW1p, tA, HsumA, HsA);
        edge_accum(sB, eB, c, l, kk, b1k, hin, ea, sW1p, tB, HsumB, HsB);

        float TAf[16], TBf[16];
#pragma unroll
        for (int jj = 0; jj < 8; jj++) {
            unpack2(tA[jj], TAf[2*jj], TAf[2*jj+1]);
            unpack2(tB[jj], TBf[2*jj], TBf[2*jj+1]);
        }

        const ulonglong2* wbase = (const ulonglong2*)(sW2 + l * SW2_PITCH);
        // dst half: rows r (coef = Hsum * h_n[r])
#pragma unroll
        for (int r = 0; r < 16; r++) {
            float cA = HsumA * __shfl_sync(0xffffffffu, hA, r);
            float cB = HsumB * __shfl_sync(0xffffffffu, hB, r);
            ull ccA = pack2(cA, cA), ccB = pack2(cB, cB);
#pragma unroll
            for (int d4 = 0; d4 < 4; d4++) {
                ulonglong2 w = wbase[r * 4 + d4];
                pA[2*d4]   = fma2(ccA, w.x, pA[2*d4]);
                pA[2*d4+1] = fma2(ccA, w.y, pA[2*d4+1]);
                pB[2*d4]   = fma2(ccB, w.x, pB[2*d4]);
                pB[2*d4+1] = fma2(ccB, w.y, pB[2*d4+1]);
            }
        }
        // src half: rows 16+j (coef = T[j])
#pragma unroll
        for (int j = 0; j < 16; j++) {
            ull ccA = pack2(TAf[j], TAf[j]), ccB = pack2(TBf[j], TBf[j]);
#pragma unroll
            for (int d4 = 0; d4 < 4; d4++) {
                ulonglong2 w = wbase[64 + j * 4 + d4];
                pA[2*d4]   = fma2(ccA, w.x, pA[2*d4]);
                pA[2*d4+1] = fma2(ccA, w.y, pA[2*d4+1]);
                pB[2*d4]   = fma2(ccB, w.x, pB[2*d4]);
                pB[2*d4+1] = fma2(ccB, w.y, pB[2*d4+1]);
            }
        }
    }

    // epilogue: unpack, add per-lane (r/j = l) terms, warp-reduce, write
    float fa[16], fb[16];
#pragma unroll
    for (int i = 0; i < 8; i++) {
        unpack2(pA[i], fa[2*i], fa[2*i+1]);
        unpack2(pB[i], fb[2*i], fb[2*i+1]);
    }
    if (l < 16) {
        float dgA = (float)(eA - sA), dgB = (float)(eB - sB);
        float c0A = dgA * hA, c0B = dgB * hB;
        const float* b2d = b2 + l * 16;
        const float* b2s = b2 + 256 + l * 16;
        const float* rt  = root + l * 16;
#pragma unroll
        for (int d = 0; d < 16; d++) {
            float bd = b2d[d], bs = b2s[d], rr = rt[d];
            fa[d] = fmaf(c0A, bd, fmaf(HsA, bs, fmaf(hA, rr, fa[d])));
            fb[d] = fmaf(c0B, bd, fmaf(HsB, bs, fmaf(hB, rr, fb[d])));
        }
    }
#pragma unroll
    for (int off = 16; off >= 1; off >>= 1) {
#pragma unroll
        for (int d = 0; d < 16; d++) {
            fa[d] += __shfl_xor_sync(0xffffffffu, fa[d], off);
            fb[d] += __shfl_xor_sync(0xffffffffu, fb[d], off);
        }
    }
    if (l < 16) {
        float vA = fa[0], vB = fb[0];
#pragma unroll
        for (int d = 1; d < 16; d++) {
            vA = (l == d) ? fa[d] : vA;
            vB = (l == d) ? fb[d] : vB;
        }
        float bl = bias[l];
        hout[(size_t)nA * 16 + l] = vA + bl;
        hout[(size_t)nB * 16 + l] = vB + bl;
    }
}

// ---------------- launch 5: edge embedding + log_softmax --------------------
__global__ void k_edge_embed(const float* __restrict__ ea,
                             const float* __restrict__ We,
                             const float* __restrict__ be,
                             float* __restrict__ ee_out,
                             float* __restrict__ lsm_out,
                             int n_ee, int n_lsm) {
    __shared__ float sW[256];
    __shared__ float sb[16];
    int tid = threadIdx.x;
    if (tid < 256) sW[tid] = We[tid];
    if (tid < 16) sb[tid] = be[tid];
    __syncthreads();
    int e = blockIdx.x * blockDim.x + tid;
    if (e >= N_EDGES) return;
    float xi[16];
    const float4* xp = (const float4*)(ea + (size_t)e * 16);
#pragma unroll
    for (int q = 0; q < 4; q++) {
        float4 v = xp[q];
        xi[4*q] = v.x; xi[4*q+1] = v.y; xi[4*q+2] = v.z; xi[4*q+3] = v.w;
    }
    float v[16];
    float m = -1e30f;
#pragma unroll
    for (int d = 0; d < 16; d++) {
        float acc = sb[d];
#pragma unroll
        for (int k = 0; k < 16; k++) acc = fmaf(xi[k], sW[k*16+d], acc);
        v[d] = fmaxf(acc, 0.f);
        m = fmaxf(m, v[d]);
    }
    float s = 0.f;
#pragma unroll
    for (int d = 0; d < 16; d++) s += expf(v[d] - m);
    float ls = m + logf(s);
    if (e < n_ee) {
        float4* eo = (float4*)(ee_out + (size_t)e * 16);
#pragma unroll
        for (int q = 0; q < 4; q++)
            eo[q] = make_float4(v[4*q], v[4*q+1], v[4*q+2], v[4*q+3]);
    }
    if (e < n_lsm) {
        float4* lo = (float4*)(lsm_out + (size_t)e * 16);
#pragma unroll
        for (int q = 0; q < 4; q++)
            lo[q] = make_float4(v[4*q] - ls, v[4*q+1] - ls, v[4*q+2] - ls, v[4*q+3] - ls);
    }
}

// ---------------- launch 6: edge_index passthrough ---------------------------
__global__ void k_ei_copy(const int* __restrict__ ei, float* __restrict__ out,
                          int n_vals) {
    int i = blockIdx.x * blockDim.x + threadIdx.x;
    if (i < n_vals) out[i] = (float)ei[i];
}

// ---------------- launch -----------------------------------------------------
extern "C" void kernel_launch(void* const* d_in, const int* in_sizes, int n_in,
                              void* d_out, int out_size) {
    const float* x     = (const float*)d_in[0];
    const int*   ei    = (const int*)d_in[1];
    const float* ea    = (const float*)d_in[2];
    const float* Wn    = (const float*)d_in[3];
    const float* bn    = (const float*)d_in[4];
    const float* We    = (const float*)d_in[5];
    const float* be    = (const float*)d_in[6];
    const float* W1    = (const float*)d_in[7];
    const float* b1    = (const float*)d_in[8];
    const float* W2    = (const float*)d_in[9];
    const float* b2    = (const float*)d_in[10];
    const float* root1 = (const float*)d_in[11];
    const float* bias1 = (const float*)d_in[12];
    const float* root2 = (const float*)d_in[13];
    const float* bias2 = (const float*)d_in[14];

    float* out = (float*)d_out;
    size_t cap = (size_t)out_size;

    // output layout derived from out_size (validated in R3/R4)
    size_t ei_slots = (cap == 13120000) ? 0 : 2ull * N_EDGES;
    size_t off_h   = 0;
    size_t off_ei  = off_h + (size_t)N_NODES * 16;
    size_t off_ee  = off_ei + ei_slots;
    size_t off_lsm = off_ee + (size_t)N_EDGES * 16;
    auto avail = [&](size_t off) -> size_t { return off < cap ? cap - off : 0; };

    float* out_h   = out + off_h;
    float* out_ei  = out + off_ei;
    float* out_ee  = out + off_ee;
    float* out_lsm = out + off_lsm;

    bool h_fits = avail(off_h) >= (size_t)N_NODES * 16;
    int  n_ei   = ei_slots ? (int)min((size_t)(2 * N_EDGES), avail(off_ei)) : 0;
    int  n_ee   = (int)min((size_t)N_EDGES, avail(off_ee) / 16);
    int  n_lsm  = (int)min((size_t)N_EDGES, avail(off_lsm) / 16);

    cudaFuncSetAttribute(k_conv, cudaFuncAttributeMaxDynamicSharedMemorySize,
                         CONV_DSMEM);

    // launch 0: degree count + node embedding (g_deg zeroed by previous run)
    k_count_embed<<<COUNT_BLOCKS + EMBED_BLOCKS, 256>>>(ei, x, Wn, bn);
    // launch 1: prefix scan (re-zeros g_cursor)
    k_scan<<<1, 1024>>>();
    // launch 2: fill dst-sorted edge list (re-zeros g_deg)
    k_fill<<<COUNT_BLOCKS, 256>>>(ei);

    // launch 3: conv layer 1 (g_h0 -> g_h1)  [profiled by ncu -s]
    k_conv<<<N_NODES / 16, CONV_T, CONV_DSMEM>>>(
        0, 1, out_h, ea, W1, b1, W2, b2, root1, bias1);
    // launch 4: conv layer 2 (g_h1 -> out_h)
    int sout2 = h_fits ? 2 : 0;
    k_conv<<<N_NODES / 16, CONV_T, CONV_DSMEM>>>(
        1, sout2, out_h, ea, W1, b1, W2, b2, root2, bias2);

    // launch 5: edge embedding + log_softmax
    if (n_ee > 0 || n_lsm > 0)
        k_edge_embed<<<(N_EDGES + 255) / 256, 256>>>(ea, We, be, out_ee, out_lsm,
                                                     n_ee, n_lsm);
    // launch 6: edge_index passthrough
    if (n_ei > 0)
        k_ei_copy<<<(n_ei + 255) / 256, 256>>>(ei, out_ei, n_ei);
}

// round 6
// speedup vs baseline: 2.1166x; 1.0003x over previous
#include <cuda_runtime.h>
#include <math.h>

#define N_NODES 20000
#define N_EDGES 400000
typedef unsigned long long ull;

// ---------------- scratch (device globals, zero-initialized) ---------------
__device__ float g_h0[N_NODES * 16];
__device__ float g_h1[N_NODES * 16];
__device__ int   g_deg[N_NODES];       // re-zeroed by k_fill each run
__device__ int   g_cursor[N_NODES];    // re-zeroed by k_scan each run
__device__ int   g_off[N_NODES + 1];
__device__ int2  g_es[N_EDGES];        // (edge id, src node) sorted by dst

__device__ __forceinline__ float* pick_buf(int s, float* ext) {
    if (s == 0) return g_h0;
    if (s == 1) return g_h1;
    return ext;
}
__device__ __forceinline__ const float* pick_cbuf(int s, const float* ext) {
    if (s == 0) return g_h0;
    if (s == 1) return g_h1;
    return ext;
}

// ---------------- f32x2 helpers ---------------------------------------------
__device__ __forceinline__ ull pack2(float a, float b) {
    ull r; asm("mov.b64 %0, {%1, %2};" : "=l"(r) : "f"(a), "f"(b)); return r;
}
__device__ __forceinline__ void unpack2(ull v, float& a, float& b) {
    asm("mov.b64 {%0, %1}, %2;" : "=f"(a), "=f"(b) : "l"(v));
}
__device__ __forceinline__ ull fma2(ull a, ull b, ull c) {
    ull d; asm("fma.rn.f32x2 %0, %1, %2, %3;" : "=l"(d) : "l"(a), "l"(b), "l"(c));
    return d;
}

// ---------------- launch 0: degree count + node embedding ------------------
#define COUNT_BLOCKS 1563           // ceil(400000/256)
#define EMBED_BLOCKS 79             // ceil(20000/256)
__global__ void k_count_embed(const int* __restrict__ ei,
                              const float* __restrict__ x,
                              const float* __restrict__ Wn,
                              const float* __restrict__ bn) {
    int b = blockIdx.x;
    if (b < COUNT_BLOCKS) {
        int e = b * 256 + threadIdx.x;
        if (e < N_EDGES) atomicAdd(&g_deg[ei[N_EDGES + e]], 1);
    } else {
        __shared__ float sW[256];
        __shared__ float sb[16];
        int tid = threadIdx.x;
        sW[tid] = Wn[tid];
        if (tid < 16) sb[tid] = bn[tid];
        __syncthreads();
        int n = (b - COUNT_BLOCKS) * 256 + tid;
        if (n >= N_NODES) return;
        float xi[16];
        const float4* xp = (const float4*)(x + (size_t)n * 16);
#pragma unroll
        for (int q = 0; q < 4; q++) {
            float4 v = xp[q];
            xi[4*q] = v.x; xi[4*q+1] = v.y; xi[4*q+2] = v.z; xi[4*q+3] = v.w;
        }
        float o[16];
#pragma unroll
        for (int d = 0; d < 16; d++) {
            float acc = sb[d];
#pragma unroll
            for (int k = 0; k < 16; k++) acc = fmaf(xi[k], sW[k*16+d], acc);
            o[d] = fmaxf(acc, 0.f);
        }
        float4* op = (float4*)(g_h0 + (size_t)n * 16);
#pragma unroll
        for (int q = 0; q < 4; q++)
            op[q] = make_float4(o[4*q], o[4*q+1], o[4*q+2], o[4*q+3]);
    }
}

// ---------------- launch 1: prefix scan (+ re-zero cursor) ------------------
__global__ void __launch_bounds__(1024) k_scan() {
    __shared__ int sm[1024];
    int t = threadIdx.x;
    int base = t * 20;
    int vals[20];
    int local = 0;
#pragma unroll
    for (int i = 0; i < 20; i++) {
        int idx = base + i;
        vals[i] = (idx < N_NODES) ? g_deg[idx] : 0;
        local += vals[i];
    }
    sm[t] = local;
    __syncthreads();
    for (int off = 1; off < 1024; off <<= 1) {
        int v = (t >= off) ? sm[t - off] : 0;
        __syncthreads();
        sm[t] += v;
        __syncthreads();
    }
    int run = sm[t] - local;
#pragma unroll
    for (int i = 0; i < 20; i++) {
        int idx = base + i;
        if (idx < N_NODES) { g_off[idx] = run; run += vals[i]; g_cursor[idx] = 0; }
    }
    if (t == 0) g_off[N_NODES] = N_EDGES;
}

// ---------------- launch 2: fill sorted edge list (+ re-zero deg) -----------
__global__ void k_fill(const int* __restrict__ ei) {
    int e = blockIdx.x * blockDim.x + threadIdx.x;
    if (e < N_EDGES) {
        int d = ei[N_EDGES + e];
        int pos = g_off[d] + atomicAdd(&g_cursor[d], 1);
        g_es[pos] = make_int2(e, ei[e]);
    }
    if (e < N_NODES) g_deg[e] = 0;
}

// ---------------- launch 3/4: fused graph conv ------------------------------
// out[n][d] = bias[d] + h[n]@root + deg(n)*Σ_r b2[r,d] h[n][r] + Σ_j b2[16+j,d] Hs[n][j]
//           + Σ_k Hsum[n][k] Σ_r W2[k][r,d] h[n][r] + Σ_{k,j} W2[k][16+j,d] T[n][k][j]
// hid recomputed on the fly: hid[e][k] = relu(b1[k] + Σ_q ea[e][q] W1[q][k]).
#define CONV_T 256
#define SW2_PITCH 516
#define CONV_DSMEM (32 * SW2_PITCH * 4)   // 66048 B

__device__ __forceinline__ void edge_accum(
    int pstart, int pend, int c, int l, int kk, float b1k,
    const float* __restrict__ hin, const float* __restrict__ ea,
    const ull* __restrict__ sW1p,
    ull T[8], float& Hsum, float& Hs) {
    for (int pos = pstart; pos < pend; pos++) {
        int2 es = g_es[pos];
        int e = es.x, s = es.y;
        if (c == 0 && l < 16) Hs += hin[(size_t)s * 16 + l];
        // uniform 16B loads of ea row and h[src] row (broadcast across lanes)
        ull ev[8], hv[8];
        const ulonglong2* eap = (const ulonglong2*)(ea + (size_t)e * 16);
        const ulonglong2* hjp = (const ulonglong2*)(hin + (size_t)s * 16);
#pragma unroll
        for (int q4 = 0; q4 < 4; q4++) {
            ulonglong2 t1 = eap[q4]; ev[2*q4] = t1.x; ev[2*q4+1] = t1.y;
            ulonglong2 t2 = hjp[q4]; hv[2*q4] = t2.x; hv[2*q4+1] = t2.y;
        }
        // hid[e][kk] via packed-q FMAs
        ull acc = pack2(b1k, 0.f);
#pragma unroll
        for (int qq = 0; qq < 8; qq++)
            acc = fma2(ev[qq], sW1p[qq * 128 + kk], acc);
        float a0, a1; unpack2(acc, a0, a1);
        float hd = fmaxf(a0 + a1, 0.f);
        Hsum += hd;
        ull hd2 = pack2(hd, hd);
#pragma unroll
        for (int jj = 0; jj < 8; jj++) T[jj] = fma2(hd2, hv[jj], T[jj]);
    }
}

__global__ void __launch_bounds__(CONV_T, 2) k_conv(
    int sin, int sout, float* ext,
    const float* __restrict__ ea,
    const float* __restrict__ W1, const float* __restrict__ b1,
    const float* __restrict__ W2, const float* __restrict__ b2,
    const float* __restrict__ root, const float* __restrict__ bias) {
    extern __shared__ float sW2[];           // [32][516] chunk of W2, k-major rows
    __shared__ ull   sW1p[8 * 128];          // (W1[2q][k], W1[2q+1][k])
    __shared__ float sB1[128];
    const float* hin = pick_cbuf(sin, ext);
    float* hout = pick_buf(sout, ext);
    int tid = threadIdx.x, wid = tid >> 5, l = tid & 31;

    for (int i = tid; i < 1024; i += CONV_T) {
        int qq = i >> 7, k = i & 127;
        sW1p[i] = pack2(W1[(2*qq) * 128 + k], W1[(2*qq+1) * 128 + k]);
    }
    if (tid < 128) sB1[tid] = b1[tid];

    int nA = blockIdx.x * 16 + wid * 2;
    int nB = nA + 1;
    int sA = g_off[nA], eA = g_off[nA + 1];
    int sB = g_off[nB], eB = g_off[nB + 1];
    float hA = (l < 16) ? hin[(size_t)nA * 16 + l] : 0.f;
    float hB = (l < 16) ? hin[(size_t)nB * 16 + l] : 0.f;

    ull pA[8], pB[8];
#pragma unroll
    for (int i = 0; i < 8; i++) { pA[i] = 0ull; pB[i] = 0ull; }
    float HsA = 0.f, HsB = 0.f;

    for (int c = 0; c < 4; c++) {
        __syncthreads();
        for (int i = tid; i < 32 * 128; i += CONV_T) {
            int kl = i >> 7, r4 = i & 127;
            float4 w = ((const float4*)W2)[(size_t)(c * 32 + kl) * 128 + r4];
            *(float4*)&sW2[kl * SW2_PITCH + r4 * 4] = w;
        }
        __syncthreads();

        int kk = c * 32 + l;
        float b1k = sB1[kk];

        ull tA[8], tB[8];
#pragma unroll
        for (int i = 0; i < 8; i++) { tA[i] = 0ull; tB[i] = 0ull; }
        float HsumA = 0.f, HsumB = 0.f;
        edge_accum(sA, eA, c, l, kk, b1k, hin, ea, sW1p, tA, HsumA, HsA);
        edge_accum(sB, eB, c, l, kk, b1k, hin, ea, sW1p, tB, HsumB, HsB);

        float TAf[16], TBf[16];
#pragma unroll
        for (int jj = 0; jj < 8; jj++) {
            unpack2(tA[jj], TAf[2*jj], TAf[2*jj+1]);
            unpack2(tB[jj], TBf[2*jj], TBf[2*jj+1]);
        }

        const ulonglong2* wbase = (const ulonglong2*)(sW2 + l * SW2_PITCH);
        // dst half: rows r (coef = Hsum * h_n[r])
#pragma unroll
        for (int r = 0; r < 16; r++) {
            float cA = HsumA * __shfl_sync(0xffffffffu, hA, r);
            float cB = HsumB * __shfl_sync(0xffffffffu, hB, r);
            ull ccA = pack2(cA, cA), ccB = pack2(cB, cB);
#pragma unroll
            for (int d4 = 0; d4 < 4; d4++) {
                ulonglong2 w = wbase[r * 4 + d4];
                pA[2*d4]   = fma2(ccA, w.x, pA[2*d4]);
                pA[2*d4+1] = fma2(ccA, w.y, pA[2*d4+1]);
                pB[2*d4]   = fma2(ccB, w.x, pB[2*d4]);
                pB[2*d4+1] = fma2(ccB, w.y, pB[2*d4+1]);
            }
        }
        // src half: rows 16+j (coef = T[j])
#pragma unroll
        for (int j = 0; j < 16; j++) {
            ull ccA = pack2(TAf[j], TAf[j]), ccB = pack2(TBf[j], TBf[j]);
#pragma unroll
            for (int d4 = 0; d4 < 4; d4++) {
                ulonglong2 w = wbase[64 + j * 4 + d4];
                pA[2*d4]   = fma2(ccA, w.x, pA[2*d4]);
                pA[2*d4+1] = fma2(ccA, w.y, pA[2*d4+1]);
                pB[2*d4]   = fma2(ccB, w.x, pB[2*d4]);
                pB[2*d4+1] = fma2(ccB, w.y, pB[2*d4+1]);
            }
        }
    }

    // epilogue: unpack, add per-lane (r/j = l) terms, warp-reduce, write
    float fa[16], fb[16];
#pragma unroll
    for (int i = 0; i < 8; i++) {
        unpack2(pA[i], fa[2*i], fa[2*i+1]);
        unpack2(pB[i], fb[2*i], fb[2*i+1]);
    }
    if (l < 16) {
        float dgA = (float)(eA - sA), dgB = (float)(eB - sB);
        float c0A = dgA * hA, c0B = dgB * hB;
        const float* b2d = b2 + l * 16;
        const float* b2s = b2 + 256 + l * 16;
        const float* rt  = root + l * 16;
#pragma unroll
        for (int d = 0; d < 16; d++) {
            float bd = b2d[d], bs = b2s[d], rr = rt[d];
            fa[d] = fmaf(c0A, bd, fmaf(HsA, bs, fmaf(hA, rr, fa[d])));
            fb[d] = fmaf(c0B, bd, fmaf(HsB, bs, fmaf(hB, rr, fb[d])));
        }
    }
#pragma unroll
    for (int off = 16; off >= 1; off >>= 1) {
#pragma unroll
        for (int d = 0; d < 16; d++) {
            fa[d] += __shfl_xor_sync(0xffffffffu, fa[d], off);
            fb[d] += __shfl_xor_sync(0xffffffffu, fb[d], off);
        }
    }
    if (l < 16) {
        float vA = fa[0], vB = fb[0];
#pragma unroll
        for (int d = 1; d < 16; d++) {
            vA = (l == d) ? fa[d] : vA;
            vB = (l == d) ? fb[d] : vB;
        }
        float bl = bias[l];
        hout[(size_t)nA * 16 + l] = vA + bl;
        hout[(size_t)nB * 16 + l] = vB + bl;
    }
}

// ---------------- launch 5: edge embedding + log_softmax --------------------
__global__ void k_edge_embed(const float* __restrict__ ea,
                             const float* __restrict__ We,
                             const float* __restrict__ be,
                             float* __restrict__ ee_out,
                             float* __restrict__ lsm_out,
                             int n_ee, int n_lsm) {
    __shared__ float sW[256];
    __shared__ float sb[16];
    int tid = threadIdx.x;
    if (tid < 256) sW[tid] = We[tid];
    if (tid < 16) sb[tid] = be[tid];
    __syncthreads();
    int e = blockIdx.x * blockDim.x + tid;
    if (e >= N_EDGES) return;
    float xi[16];
    const float4* xp = (const float4*)(ea + (size_t)e * 16);
#pragma unroll
    for (int q = 0; q < 4; q++) {
        float4 v = xp[q];
        xi[4*q] = v.x; xi[4*q+1] = v.y; xi[4*q+2] = v.z; xi[4*q+3] = v.w;
    }
    float v[16];
    float m = -1e30f;
#pragma unroll
    for (int d = 0; d < 16; d++) {
        float acc = sb[d];
#pragma unroll
        for (int k = 0; k < 16; k++) acc = fmaf(xi[k], sW[k*16+d], acc);
        v[d] = fmaxf(acc, 0.f);
        m = fmaxf(m, v[d]);
    }
    float s = 0.f;
#pragma unroll
    for (int d = 0; d < 16; d++) s += expf(v[d] - m);
    float ls = m + logf(s);
    if (e < n_ee) {
        float4* eo = (float4*)(ee_out + (size_t)e * 16);
#pragma unroll
        for (int q = 0; q < 4; q++)
            eo[q] = make_float4(v[4*q], v[4*q+1], v[4*q+2], v[4*q+3]);
    }
    if (e < n_lsm) {
        float4* lo = (float4*)(lsm_out + (size_t)e * 16);
#pragma unroll
        for (int q = 0; q < 4; q++)
            lo[q] = make_float4(v[4*q] - ls, v[4*q+1] - ls, v[4*q+2] - ls, v[4*q+3] - ls);
    }
}

// ---------------- launch 6: edge_index passthrough ---------------------------
__global__ void k_ei_copy(const int* __restrict__ ei, float* __restrict__ out,
                          int n_vals) {
    int i = blockIdx.x * blockDim.x + threadIdx.x;
    if (i < n_vals) out[i] = (float)ei[i];
}

// ---------------- launch -----------------------------------------------------
extern "C" void kernel_launch(void* const* d_in, const int* in_sizes, int n_in,
                              void* d_out, int out_size) {
    const float* x     = (const float*)d_in[0];
    const int*   ei    = (const int*)d_in[1];
    const float* ea    = (const float*)d_in[2];
    const float* Wn    = (const float*)d_in[3];
    const float* bn    = (const float*)d_in[4];
    const float* We    = (const float*)d_in[5];
    const float* be    = (const float*)d_in[6];
    const float* W1    = (const float*)d_in[7];
    const float* b1    = (const float*)d_in[8];
    const float* W2    = (const float*)d_in[9];
    const float* b2    = (const float*)d_in[10];
    const float* root1 = (const float*)d_in[11];
    const float* bias1 = (const float*)d_in[12];
    const float* root2 = (const float*)d_in[13];
    const float* bias2 = (const float*)d_in[14];

    float* out = (float*)d_out;
    size_t cap = (size_t)out_size;

    // output layout derived from out_size (validated in R3/R4)
    size_t ei_slots = (cap == 13120000) ? 0 : 2ull * N_EDGES;
    size_t off_h   = 0;
    size_t off_ei  = off_h + (size_t)N_NODES * 16;
    size_t off_ee  = off_ei + ei_slots;
    size_t off_lsm = off_ee + (size_t)N_EDGES * 16;
    auto avail = [&](size_t off) -> size_t { return off < cap ? cap - off : 0; };

    float* out_h   = out + off_h;
    float* out_ei  = out + off_ei;
    float* out_ee  = out + off_ee;
    float* out_lsm = out + off_lsm;

    bool h_fits = avail(off_h) >= (size_t)N_NODES * 16;
    int  n_ei   = ei_slots ? (int)min((size_t)(2 * N_EDGES), avail(off_ei)) : 0;
    int  n_ee   = (int)min((size_t)N_EDGES, avail(off_ee) / 16);
    int  n_lsm  = (int)min((size_t)N_EDGES, avail(off_lsm) / 16);

    cudaFuncSetAttribute(k_conv, cudaFuncAttributeMaxDynamicSharedMemorySize,
                         CONV_DSMEM);

    // launch 0: degree count + node embedding (g_deg zeroed by previous run)
    k_count_embed<<<COUNT_BLOCKS + EMBED_BLOCKS, 256>>>(ei, x, Wn, bn);
    // launch 1: prefix scan (re-zeros g_cursor)
    k_scan<<<1, 1024>>>();
    // launch 2: fill dst-sorted edge list (re-zeros g_deg)
    k_fill<<<COUNT_BLOCKS, 256>>>(ei);

    // launch 3: conv layer 1 (g_h0 -> g_h1)  [profiled by ncu -s]
    k_conv<<<N_NODES / 16, CONV_T, CONV_DSMEM>>>(
        0, 1, out_h, ea, W1, b1, W2, b2, root1, bias1);
    // launch 4: conv layer 2 (g_h1 -> out_h)
    int sout2 = h_fits ? 2 : 0;
    k_conv<<<N_NODES / 16, CONV_T, CONV_DSMEM>>>(
        1, sout2, out_h, ea, W1, b1, W2, b2, root2, bias2);

    // launch 5: edge embedding + log_softmax
    if (n_ee > 0 || n_lsm > 0)
        k_edge_embed<<<(N_EDGES + 255) / 256, 256>>>(ea, We, be, out_ee, out_lsm,
                                                     n_ee, n_lsm);
    // launch 6: edge_index passthrough
    if (n_ei > 0)
        k_ei_copy<<<(n_ei + 255) / 256, 256>>>(ei, out_ei, n_ei);
}